// round 15
// baseline (speedup 1.0000x reference)
#include <cuda_runtime.h>
#include <cuda_bf16.h>
#include <math.h>

#define BB 8
#define SS 1024
#define DD 512
#define HH 8
#define DKK 64
#define NEGV -1e32f
#define BSD (BB*SS*DD)   /* 4194304 */

__device__ float g_scratch[(size_t)8 * BSD];

// ---------------- packed fp32x2 helpers ----------------
#define FMA2(c, a, b) asm("fma.rn.f32x2 %0, %1, %2, %0;" : "+l"(c) : "l"(a), "l"(b))
#define UNPK(lo, hi, p) asm("mov.b64 {%0,%1}, %2;" : "=f"(lo), "=f"(hi) : "l"(p))
__device__ __forceinline__ unsigned long long pk2(float lo, float hi) {
  unsigned long long r; asm("mov.b64 %0, {%1,%2};" : "=l"(r) : "f"(lo), "f"(hi)); return r;
}
__device__ __forceinline__ unsigned long long pk1(float v) { return pk2(v, v); }

// ---------------------------------------------------------------------------
// FMA2 GEMM core (R5, proven), parametrized by block coords (bx, by).
// ---------------------------------------------------------------------------
__device__ __forceinline__ void gemm2_body(
    const float* __restrict__ A, int lda,
    const float* __restrict__ W0, const float* __restrict__ W1,
    const float* __restrict__ bias0, const float* __restrict__ bias1,
    float* __restrict__ C0, float* __restrict__ C1, int K, int N1,
    int bx, int by,
    float (*As)[132], float (*Ws)[132])   // [2*8][132] each
{
  const int tid = threadIdx.x;
  const int tx = tid & 15, ty = tid >> 4;
  const int m0 = by * 128;
  const int n0g = bx * 128;
  const float* W; const float* bias; float* C; int n0;
  if (n0g < N1) { W = W0; bias = bias0; C = C0; n0 = n0g; }
  else          { W = W1; bias = bias1; C = C1; n0 = n0g - N1; }

  const int arow = tid >> 1, akq = (tid & 1) * 4;
  const int wkr = tid >> 5, wc4 = (tid & 31) * 4;
  const float* Aptr = A + (size_t)(m0 + arow)*lda + akq;
  const float* Wptr = W + (size_t)wkr*512 + n0 + wc4;

  unsigned long long acc[2][4][2][2];
  #pragma unroll
  for (int ih = 0; ih < 2; ih++)
    #pragma unroll
    for (int i = 0; i < 4; i++)
      #pragma unroll
      for (int jh = 0; jh < 2; jh++)
        { acc[ih][i][jh][0] = 0ull; acc[ih][i][jh][1] = 0ull; }

  {
    float4 va = *(const float4*)Aptr;
    float4 vw = *(const float4*)Wptr;
    As[0*8 + akq+0][arow] = va.x;
    As[0*8 + akq+1][arow] = va.y;
    As[0*8 + akq+2][arow] = va.z;
    As[0*8 + akq+3][arow] = va.w;
    *(float4*)&Ws[0*8 + wkr][wc4] = vw;
  }
  __syncthreads();

  const int nch = K >> 3;
  for (int c = 0; c < nch; c++) {
    int buf = c & 1;
    bool more = (c + 1) < nch;
    float4 na, nw;
    if (more) {
      na = *(const float4*)(Aptr + (c+1)*8);
      nw = *(const float4*)(Wptr + (size_t)(c+1)*8*512);
    }
    #pragma unroll
    for (int k = 0; k < 8; k++) {
      float4 a0 = *(const float4*)&As[buf*8 + k][ty*4];
      float4 a1 = *(const float4*)&As[buf*8 + k][64 + ty*4];
      float4 w0 = *(const float4*)&Ws[buf*8 + k][tx*4];
      float4 w1 = *(const float4*)&Ws[buf*8 + k][64 + tx*4];
      unsigned long long bp[2][2];
      bp[0][0] = pk2(w0.x, w0.y); bp[0][1] = pk2(w0.z, w0.w);
      bp[1][0] = pk2(w1.x, w1.y); bp[1][1] = pk2(w1.z, w1.w);
      unsigned long long ap[2][4];
      ap[0][0] = pk1(a0.x); ap[0][1] = pk1(a0.y); ap[0][2] = pk1(a0.z); ap[0][3] = pk1(a0.w);
      ap[1][0] = pk1(a1.x); ap[1][1] = pk1(a1.y); ap[1][2] = pk1(a1.z); ap[1][3] = pk1(a1.w);
      #pragma unroll
      for (int ih = 0; ih < 2; ih++)
        #pragma unroll
        for (int i = 0; i < 4; i++)
          #pragma unroll
          for (int jh = 0; jh < 2; jh++) {
            FMA2(acc[ih][i][jh][0], ap[ih][i], bp[jh][0]);
            FMA2(acc[ih][i][jh][1], ap[ih][i], bp[jh][1]);
          }
    }
    if (more) {
      int nb = buf ^ 1;
      As[nb*8 + akq+0][arow] = na.x;
      As[nb*8 + akq+1][arow] = na.y;
      As[nb*8 + akq+2][arow] = na.z;
      As[nb*8 + akq+3][arow] = na.w;
      *(float4*)&Ws[nb*8 + wkr][wc4] = nw;
      __syncthreads();
    }
  }

  #pragma unroll
  for (int ih = 0; ih < 2; ih++)
    #pragma unroll
    for (int i = 0; i < 4; i++) {
      int row = m0 + ih*64 + ty*4 + i;
      #pragma unroll
      for (int jh = 0; jh < 2; jh++) {
        int cn = n0 + jh*64 + tx*4;
        float4 o;
        UNPK(o.x, o.y, acc[ih][i][jh][0]);
        UNPK(o.z, o.w, acc[ih][i][jh][1]);
        o.x += bias[cn+0]; o.y += bias[cn+1]; o.z += bias[cn+2]; o.w += bias[cn+3];
        *(float4*)&C[(size_t)row*512 + cn] = o;
      }
    }
}

__global__ __launch_bounds__(256) void gemm2_kernel(
    const float* __restrict__ A, int lda,
    const float* __restrict__ W0, const float* __restrict__ W1,
    const float* __restrict__ bias0, const float* __restrict__ bias1,
    float* __restrict__ C0, float* __restrict__ C1, int K, int N1)
{
  __shared__ float As[16][132];
  __shared__ float Ws[16][132];
  gemm2_body(A, lda, W0, W1, bias0, bias1, C0, C1, K, N1,
             blockIdx.x, blockIdx.y, As, Ws);
}

// z-batched variant: blockIdx.z selects between two independent GEMM problems
__global__ __launch_bounds__(256) void gemm2z_kernel(
    const float* __restrict__ A0, const float* __restrict__ A1,
    const float* __restrict__ W00, const float* __restrict__ W01,
    const float* __restrict__ W10, const float* __restrict__ W11,
    const float* __restrict__ b00, const float* __restrict__ b01,
    const float* __restrict__ b10, const float* __restrict__ b11,
    float* __restrict__ C00, float* __restrict__ C01,
    float* __restrict__ C10, float* __restrict__ C11,
    int K, int N1)
{
  __shared__ float As[16][132];
  __shared__ float Ws[16][132];
  if (blockIdx.z == 0)
    gemm2_body(A0, 512, W00, W01, b00, b01, C00, C01, K, N1,
               blockIdx.x, blockIdx.y, As, Ws);
  else
    gemm2_body(A1, 512, W10, W11, b10, b11, C10, C11, K, N1,
               blockIdx.x, blockIdx.y, As, Ws);
}

// 3-segment GEMM: seg = blockIdx.x>>2 in {0,1,2}
__global__ __launch_bounds__(256) void gemm_seg3_kernel(
    const float* __restrict__ A01, const float* __restrict__ A2,
    const float* __restrict__ Wg0, const float* __restrict__ bg0, float* __restrict__ Cg0,
    const float* __restrict__ Wg1, const float* __restrict__ bg1, float* __restrict__ Cg1,
    const float* __restrict__ Wg2, const float* __restrict__ bg2, float* __restrict__ Cg2)
{
  __shared__ float As[16][132];
  __shared__ float Ws[16][132];
  int seg = blockIdx.x >> 2;
  int bx = blockIdx.x & 3;
  const float* A = (seg == 2) ? A2 : A01;
  const float* W = (seg == 0) ? Wg0 : (seg == 1) ? Wg1 : Wg2;
  const float* bs = (seg == 0) ? bg0 : (seg == 1) ? bg1 : bg2;
  float* C = (seg == 0) ? Cg0 : (seg == 1) ? Cg1 : Cg2;
  gemm2_body(A, 512, W, W, bs, bs, C, C, 512, 512, bx, blockIdx.y, As, Ws);
}

// ---------------------------------------------------------------------------
// Causal attention — R13 core with row-max FUSED into phase 1 (registers +
// one shfl reduce) — phase-2 max sweep removed.
// ---------------------------------------------------------------------------
template<int MODE>
__device__ __forceinline__ bool msk2(int gi, int j) {
  return (MODE == 0) ? (j <= gi) : (j < gi);
}

template<int MODE, int MAXOUT>
__global__ __launch_bounds__(256) void attn2_kernel(
    const float* __restrict__ qk0, const float* __restrict__ v0,
    float* __restrict__ out0,
    const float* __restrict__ qk1, const float* __restrict__ v1,
    float* __restrict__ out1,
    const float* __restrict__ gamma)
{
  extern __shared__ float sm[];
  float* srow  = sm;                    // 32 * 1024
  float* qs    = srow + 32*SS;          // 32 * 68
  float* ks    = qs + 32*68;            // 128 * 68 (K tile, reused for V)
  float* csumA = ks + 128*68;           // 8 warps * 4 rows * 32

  int i0 = blockIdx.x * 32;
  int h  = blockIdx.y;
  int zz = blockIdx.z;
  int strm = zz >> 3;
  int b  = zz & 7;
  const float* qk = strm ? qk1 : qk0;
  const float* v  = strm ? v1  : v0;
  float* out      = strm ? out1 : out0;
  const float* gm = gamma + strm*HH;

  int tid = threadIdx.x;
  int lane = tid & 31, wi = tid >> 5;
  int tj = lane;
  const float* qbase = qk + (size_t)b*SS*DD + h*DKK;
  const float* vbase = v  + (size_t)b*SS*DD + h*DKK;
  int jlim = i0 + 32;

  for (int idx = tid; idx < 32*16; idx += 256) {
    int i = idx >> 4, dc = (idx & 15) << 2;
    *(float4*)&qs[i*68 + dc] = *(const float4*)&qbase[(size_t)(i0 + i)*DD + dc];
  }

  // ---- phase 1: scores + fused row max ----
  float mx[4] = {-INFINITY, -INFINITY, -INFINITY, -INFINITY};
  for (int j0 = 0; j0 < jlim; j0 += 128) {
    __syncthreads();
    for (int idx = tid; idx < 128*16; idx += 256) {
      int rj = idx >> 4, dc = (idx & 15) << 2;
      *(float4*)&ks[rj*68 + dc] = *(const float4*)&qbase[(size_t)(j0 + rj)*DD + dc];
    }
    __syncthreads();
    float acc[4][4] = {};
    #pragma unroll
    for (int d4 = 0; d4 < 16; d4++) {
      float4 kf[4];
      #pragma unroll
      for (int u = 0; u < 4; u++)
        kf[u] = *(const float4*)&ks[(tj + 32*u)*68 + d4*4];
      #pragma unroll
      for (int r = 0; r < 4; r++) {
        float4 qf = *(const float4*)&qs[(wi*4 + r)*68 + d4*4];
        #pragma unroll
        for (int u = 0; u < 4; u++) {
          acc[r][u] = fmaf(qf.x, kf[u].x, acc[r][u]);
          acc[r][u] = fmaf(qf.y, kf[u].y, acc[r][u]);
          acc[r][u] = fmaf(qf.z, kf[u].z, acc[r][u]);
          acc[r][u] = fmaf(qf.w, kf[u].w, acc[r][u]);
        }
      }
    }
    #pragma unroll
    for (int r = 0; r < 4; r++) {
      int gi = i0 + wi*4 + r;
      #pragma unroll
      for (int u = 0; u < 4; u++) {
        int j = j0 + tj + 32*u;
        float sv = msk2<MODE>(gi, j) ? acc[r][u]*0.125f : NEGV;
        srow[(wi*4 + r)*SS + j] = sv;
        mx[r] = fmaxf(mx[r], sv);
      }
    }
  }
  __syncwarp();
  #pragma unroll
  for (int o = 16; o; o >>= 1)
    #pragma unroll
    for (int r = 0; r < 4; r++) mx[r] = fmaxf(mx[r], __shfl_xor_sync(0xffffffffu, mx[r], o));

  // ---- phase 2: 4-row-interleaved (max sweep eliminated) ----
  float gmv = -fabsf(gm[h]);
  int nc = blockIdx.x + 1;                 // 32-col chunks
  float* csums = csumA + wi*128;           // [4][32]
  float* rows[4];
  #pragma unroll
  for (int r = 0; r < 4; r++) rows[r] = srow + (wi*4 + r)*SS;
  const int gib = i0 + wi*4;

  for (int c = 0; c < nc; c++) {
    int j = c*32 + lane;
    float t[4];
    #pragma unroll
    for (int r = 0; r < 4; r++) t[r] = __expf(rows[r][j] - mx[r]);
    #pragma unroll
    for (int o = 16; o; o >>= 1)
      #pragma unroll
      for (int r = 0; r < 4; r++) t[r] += __shfl_xor_sync(0xffffffffu, t[r], o);
    if (lane == 0) {
      #pragma unroll
      for (int r = 0; r < 4; r++) csums[r*32 + c] = t[r];
    }
  }
  __syncwarp();

  float csv[4], incl[4], base[4], invz[4];
  #pragma unroll
  for (int r = 0; r < 4; r++) { csv[r] = (lane < nc) ? csums[r*32 + lane] : 0.f; incl[r] = csv[r]; }
  #pragma unroll
  for (int o = 1; o < 32; o <<= 1)
    #pragma unroll
    for (int r = 0; r < 4; r++) {
      float t = __shfl_up_sync(0xffffffffu, incl[r], o);
      if (lane >= o) incl[r] += t;
    }
  #pragma unroll
  for (int r = 0; r < 4; r++) {
    float z = __shfl_sync(0xffffffffu, incl[r], 31);
    base[r] = incl[r] - csv[r];
    invz[r] = __fdividef(1.f, z);
  }

  float m2[4] = {-INFINITY, -INFINITY, -INFINITY, -INFINITY};
  for (int c = 0; c < nc; c++) {
    int j = c*32 + lane;
    float sv[4], e[4];
    #pragma unroll
    for (int r = 0; r < 4; r++) { sv[r] = rows[r][j]; e[r] = __expf(sv[r] - mx[r]); }
    #pragma unroll
    for (int o = 1; o < 32; o <<= 1)
      #pragma unroll
      for (int r = 0; r < 4; r++) {
        float t = __shfl_up_sync(0xffffffffu, e[r], o);
        if (lane >= o) e[r] += t;
      }
    #pragma unroll
    for (int r = 0; r < 4; r++) {
      float cum = (__shfl_sync(0xffffffffu, base[r], c) + e[r]) * invz[r];
      float rem = 1.f - cum;
      float pos = fabsf((float)(gib + r - j));
      float dist = sqrtf(fmaxf(rem * pos, 0.f));
      float dec = fminf(fmaxf(__expf(dist * gmv), 1e-5f), 1e5f);
      float s2 = msk2<MODE>(gib + r, j) ? sv[r] * dec : NEGV;
      rows[r][j] = s2;
      m2[r] = fmaxf(m2[r], s2);
    }
  }
  #pragma unroll
  for (int o = 16; o; o >>= 1)
    #pragma unroll
    for (int r = 0; r < 4; r++) m2[r] = fmaxf(m2[r], __shfl_xor_sync(0xffffffffu, m2[r], o));

  float z2[4] = {0.f, 0.f, 0.f, 0.f};
  for (int c = 0; c < nc; c++) {
    int j = c*32 + lane;
    #pragma unroll
    for (int r = 0; r < 4; r++) {
      float e2 = __expf(rows[r][j] - m2[r]);
      rows[r][j] = e2; z2[r] += e2;
    }
  }
  #pragma unroll
  for (int o = 16; o; o >>= 1)
    #pragma unroll
    for (int r = 0; r < 4; r++) z2[r] += __shfl_xor_sync(0xffffffffu, z2[r], o);
  float scl[4];
  #pragma unroll
  for (int r = 0; r < 4; r++) {
    scl[r] = __fdividef(1.f, z2[r]);
    if (MAXOUT) scl[r] *= fminf(z2[r], 5.f);
  }
  for (int c = 0; c < nc; c++) {
    int j = c*32 + lane;
    #pragma unroll
    for (int r = 0; r < 4; r++)
      rows[r][j] = msk2<MODE>(gib + r, j) ? rows[r][j]*scl[r] : 0.f;
  }

  // ---- phase 3: out = A @ V ----
  float oa[4][2] = {};
  int d0 = 2*lane;
  for (int j0 = 0; j0 < jlim; j0 += 128) {
    __syncthreads();
    for (int idx = tid; idx < 128*16; idx += 256) {
      int rj = idx >> 4, dc = (idx & 15) << 2;
      *(float4*)&ks[rj*68 + dc] = *(const float4*)&vbase[(size_t)(j0 + rj)*DD + dc];
    }
    __syncthreads();
    int lim = jlim - j0; if (lim > 128) lim = 128;
    for (int jq = 0; jq < lim; jq += 4) {
      float4 af[4];
      #pragma unroll
      for (int r = 0; r < 4; r++)
        af[r] = *(const float4*)&srow[(wi*4 + r)*SS + j0 + jq];
      #pragma unroll
      for (int u = 0; u < 4; u++) {
        float2 vv = *(const float2*)&ks[(jq + u)*68 + d0];
        #pragma unroll
        for (int r = 0; r < 4; r++) {
          float a = (u == 0) ? af[r].x : (u == 1) ? af[r].y : (u == 2) ? af[r].z : af[r].w;
          oa[r][0] = fmaf(a, vv.x, oa[r][0]);
          oa[r][1] = fmaf(a, vv.y, oa[r][1]);
        }
      }
    }
  }
  #pragma unroll
  for (int r = 0; r < 4; r++) {
    float2 st; st.x = oa[r][0]; st.y = oa[r][1];
    *(float2*)&out[((size_t)b*SS + i0 + wi*4 + r)*DD + h*DKK + d0] = st;
  }
}

// ---------------------------------------------------------------------------
// Window attention (19 cols), one warp per (b,h,i)
// ---------------------------------------------------------------------------
__global__ __launch_bounds__(256) void win_kernel(
    const float* __restrict__ qw, const float* __restrict__ v,
    float* __restrict__ out, const float* __restrict__ gamma)
{
  int i = blockIdx.x;
  int b = blockIdx.y;
  int h = threadIdx.x >> 5;
  int lane = threadIdx.x & 31;
  const float* qbase = qw + (size_t)b*SS*DD + h*DKK;
  const float* vbase = v  + (size_t)b*SS*DD + h*DKK;
  float* obase = out + ((size_t)b*SS + i)*DD + h*DKK;
  int d0 = 2*lane;

  int wstart = i - 19; if (wstart < 0) wstart = 0;
  int n = i - wstart;
  if (n == 0) {
    float2 zz; zz.x = 0.f; zz.y = 0.f;
    *(float2*)(obase + d0) = zz;
    return;
  }
  bool act = lane < n;
  int j = wstart + lane;

  float s = NEGV;
  if (act) {
    const float4* q4 = (const float4*)(qbase + (size_t)i*DD);
    const float4* k4 = (const float4*)(qbase + (size_t)j*DD);
    float acc = 0.f;
    #pragma unroll
    for (int d4 = 0; d4 < 16; d4++) {
      float4 qa = q4[d4], kv = k4[d4];
      acc = fmaf(qa.x, kv.x, acc);
      acc = fmaf(qa.y, kv.y, acc);
      acc = fmaf(qa.z, kv.z, acc);
      acc = fmaf(qa.w, kv.w, acc);
    }
    s = acc * 0.125f;
  }
  float m = s;
  #pragma unroll
  for (int o = 16; o; o >>= 1) m = fmaxf(m, __shfl_xor_sync(0xffffffffu, m, o));
  float e = __expf(s - m);
  float incl = e;
  #pragma unroll
  for (int o = 1; o < 32; o <<= 1) {
    float t = __shfl_up_sync(0xffffffffu, incl, o);
    if (lane >= o) incl += t;
  }
  float z = __shfl_sync(0xffffffffu, incl, 31);
  float cum = incl * __fdividef(1.f, z);
  float rem = 1.f - cum;
  float pos = fabsf((float)(i - j));
  float dist = sqrtf(fmaxf(rem * pos, 0.f));
  float gmv = -fabsf(gamma[h]);
  float dec = fminf(fmaxf(__expf(dist * gmv), 1e-5f), 1e5f);
  float s2 = act ? s * dec : NEGV;
  float m2 = s2;
  #pragma unroll
  for (int o = 16; o; o >>= 1) m2 = fmaxf(m2, __shfl_xor_sync(0xffffffffu, m2, o));
  float e2 = __expf(s2 - m2);
  float z2 = e2;
  #pragma unroll
  for (int o = 16; o; o >>= 1) z2 += __shfl_xor_sync(0xffffffffu, z2, o);
  float a = act ? e2 * __fdividef(1.f, z2) : 0.f;

  float o0 = 0.f, o1 = 0.f;
  for (int jj = 0; jj < n; jj++) {
    float aj = __shfl_sync(0xffffffffu, a, jj);
    float2 vv = *(const float2*)(vbase + (size_t)(wstart + jj)*DD + d0);
    o0 = fmaf(aj, vv.x, o0);
    o1 = fmaf(aj, vv.y, o1);
  }
  float2 st; st.x = o0; st.y = o1;
  *(float2*)(obase + d0) = st;
}

// ---------------------------------------------------------------------------
// LayerNorm(x + y), z-batched over two independent problems (blockIdx.y)
// ---------------------------------------------------------------------------
__global__ __launch_bounds__(128) void ln_res_z_kernel(
    const float* __restrict__ x0, const float* __restrict__ y0,
    const float* __restrict__ lw0, const float* __restrict__ lb0,
    float* __restrict__ o0,
    const float* __restrict__ x1, const float* __restrict__ y1,
    const float* __restrict__ lw1, const float* __restrict__ lb1,
    float* __restrict__ o1)
{
  __shared__ float sb1[4], sb2[4];
  size_t row = blockIdx.x;
  const float* x; const float* y; const float* lw; const float* lb; float* out;
  if (blockIdx.y == 0) { x = x0; y = y0; lw = lw0; lb = lb0; out = o0; }
  else                 { x = x1; y = y1; lw = lw1; lb = lb1; out = o1; }
  const float* xr = x + row*DD;
  const float* yr = y + row*DD;
  int tid = threadIdx.x, lane = tid & 31, w = tid >> 5;
  float v[4]; float s = 0.f, q = 0.f;
  #pragma unroll
  for (int u = 0; u < 4; u++) {
    int c = tid + u*128;
    float t = xr[c] + yr[c];
    v[u] = t; s += t; q += t*t;
  }
  #pragma unroll
  for (int o = 16; o; o >>= 1) { s += __shfl_xor_sync(0xffffffffu, s, o); q += __shfl_xor_sync(0xffffffffu, q, o); }
  if (lane == 0) { sb1[w] = s; sb2[w] = q; }
  __syncthreads();
  s = sb1[0]+sb1[1]+sb1[2]+sb1[3];
  q = sb2[0]+sb2[1]+sb2[2]+sb2[3];
  float mu = s * (1.f/DD);
  float var = q * (1.f/DD) - mu*mu;
  float rs = rsqrtf(var + 1e-5f);
  #pragma unroll
  for (int u = 0; u < 4; u++) {
    int c = tid + u*128;
    out[row*DD + c] = (v[u]-mu)*rs*lw[c] + lb[c];
  }
}

// ---------------------------------------------------------------------------
// X[:, :512] = LN(hq+o), X[:, 512:] = LN(hq+o+ow)   (X has ld 1024)
// ---------------------------------------------------------------------------
__global__ __launch_bounds__(128) void fuse3_kernel(
    const float* __restrict__ hq, const float* __restrict__ o,
    const float* __restrict__ ow,
    const float* __restrict__ lw, const float* __restrict__ lb,
    float* __restrict__ X)
{
  __shared__ float sbuf[4][4];
  size_t row = blockIdx.x;
  int tid = threadIdx.x, lane = tid & 31, w = tid >> 5;
  const float* hr = hq + row*DD;
  const float* orr = o + row*DD;
  const float* owr = ow + row*DD;
  float v1[4], v2[4]; float st[4] = {0.f,0.f,0.f,0.f};
  #pragma unroll
  for (int u = 0; u < 4; u++) {
    int c = tid + u*128;
    float a  = hr[c] + orr[c];
    float b2 = a + owr[c];
    v1[u] = a; v2[u] = b2;
    st[0] += a;  st[1] += a*a;
    st[2] += b2; st[3] += b2*b2;
  }
  #pragma unroll
  for (int k = 0; k < 4; k++)
    #pragma unroll
    for (int o2 = 16; o2; o2 >>= 1) st[k] += __shfl_xor_sync(0xffffffffu, st[k], o2);
  if (lane == 0) { sbuf[0][w]=st[0]; sbuf[1][w]=st[1]; sbuf[2][w]=st[2]; sbuf[3][w]=st[3]; }
  __syncthreads();
  #pragma unroll
  for (int k = 0; k < 4; k++) st[k] = sbuf[k][0]+sbuf[k][1]+sbuf[k][2]+sbuf[k][3];
  float mu1 = st[0]*(1.f/DD), var1 = st[1]*(1.f/DD) - mu1*mu1;
  float mu2 = st[2]*(1.f/DD), var2 = st[3]*(1.f/DD) - mu2*mu2;
  float rs1 = rsqrtf(var1 + 1e-5f);
  float rs2 = rsqrtf(var2 + 1e-5f);
  #pragma unroll
  for (int u = 0; u < 4; u++) {
    int c = tid + u*128;
    X[row*1024 + c]       = (v1[u]-mu1)*rs1*lw[c] + lb[c];
    X[row*1024 + 512 + c] = (v2[u]-mu2)*rs2*lw[c] + lb[c];
  }
}

// ---------------------------------------------------------------------------
extern "C" void kernel_launch(void* const* d_in, const int* in_sizes, int n_in,
                              void* d_out, int out_size)
{
  const float* q_emb  = (const float*)d_in[0];
  const float* s_emb  = (const float*)d_in[1];
  const float* Wq     = (const float*)d_in[2];
  const float* bq     = (const float*)d_in[3];
  const float* Wqw    = (const float*)d_in[4];
  const float* bqw    = (const float*)d_in[5];
  const float* Wv     = (const float*)d_in[6];
  const float* bv     = (const float*)d_in[7];
  const float* Wo     = (const float*)d_in[8];
  const float* bo     = (const float*)d_in[9];
  const float* Wow    = (const float*)d_in[10];
  const float* bow    = (const float*)d_in[11];
  const float* gammas = (const float*)d_in[12];
  const float* ln_w   = (const float*)d_in[13];
  const float* ln_b   = (const float*)d_in[14];
  const float* Wc     = (const float*)d_in[15];
  const float* bc     = (const float*)d_in[16];
  float* outp = (float*)d_out;

  float* scratch = nullptr;
  cudaGetSymbolAddress((void**)&scratch, g_scratch);
  float* t0 = scratch;
  float* t1 = scratch + 1*(size_t)BSD;
  float* t2 = scratch + 2*(size_t)BSD;
  float* t3 = scratch + 3*(size_t)BSD;
  float* t4 = scratch + 4*(size_t)BSD;
  float* t5 = scratch + 5*(size_t)BSD;
  float* s6 = scratch + 6*(size_t)BSD;
  float* s7 = scratch + 7*(size_t)BSD;
  float* X  = t4;                        // [8192,1024] spans t4..t5 (used in tail)
  float* hqo = outp + (size_t)BSD;
  float* hso = outp + 2*(size_t)BSD;

  const int SMEM_ATTN = (32*SS + 32*68 + 128*68 + 8*128) * (int)sizeof(float); // 178688 B
  cudaFuncSetAttribute(attn2_kernel<0,0>, cudaFuncAttributeMaxDynamicSharedMemorySize, SMEM_ATTN);
  cudaFuncSetAttribute(attn2_kernel<1,1>, cudaFuncAttributeMaxDynamicSharedMemorySize, SMEM_ATTN);

  dim3 gdualz(8, 64, 2), gsingz(4, 64, 2);
  dim3 gseg3(12, 64);
  dim3 gsing(4, 64);
  dim3 gaz(SS/32, HH, 2*BB);
  dim3 ga1(SS/32, HH, BB);
  dim3 gw(SS, BB);
  dim3 glnz(BB*SS, 2);
  size_t DDl = (size_t)DD*DD;

  // ---- blocks 1+2 merged (independent streams) ----
  gemm2z_kernel<<<gdualz, 256>>>(q_emb, s_emb,
                                 Wq, Wv, Wq + DDl, Wv + DDl,
                                 bq, bv, bq + DD, bv + DD,
                                 t0, t1, s6, s7, 512, 512);
  attn2_kernel<0,0><<<gaz, 256, SMEM_ATTN>>>(t0, t1, t2, s6, s7, t4, gammas);
  gemm2z_kernel<<<gsingz, 256>>>(t2, t4,
                                 Wo, Wo, Wo + DDl, Wo + DDl,
                                 bo, bo, bo + DD, bo + DD,
                                 t3, t3, t5, t5, 512, 512);
  ln_res_z_kernel<<<glnz, 128>>>(q_emb, t3, ln_w, ln_b, hqo,
                                 s_emb, t5, ln_w + DD, ln_b + DD, hso);

  // ---- block 3 ----
  gemm_seg3_kernel<<<gseg3, 256>>>(hqo, hso,
                                   Wq + 2*DDl, bq + 2*DD, t0,
                                   Wqw + 2*DDl, bqw + 2*DD, s6,
                                   Wv + 2*DDl, bv + 2*DD, t1);
  win_kernel<<<gw, 256>>>(s6, t1, t4, gammas + 2*HH);
  attn2_kernel<1,1><<<ga1, 256, SMEM_ATTN>>>(t0, t1, t2, t0, t1, t2, gammas + 2*HH);
  gemm2z_kernel<<<gsingz, 256>>>(t2, t4,
                                 Wo + 2*DDl, Wo + 2*DDl, Wow, Wow,
                                 bo + 2*DD, bo + 2*DD, bow, bow,
                                 t3, t3, t0, t0, 512, 512);

  // ---- X = [LN(hq+o) | LN(hq+o+ow)] ; out = X @ Wc + bc ----
  fuse3_kernel<<<BB*SS, 128>>>(hqo, t3, t0, ln_w + 2*DD, ln_b + 2*DD, X);
  gemm2_kernel<<<gsing, 256>>>(X, 1024, Wc, Wc, bc, bc, outp, outp, 1024, 512);
}

// round 16
// speedup vs baseline: 1.0192x; 1.0192x over previous
#include <cuda_runtime.h>
#include <cuda_bf16.h>
#include <math.h>

#define BB 8
#define SS 1024
#define DD 512
#define HH 8
#define DKK 64
#define NEGV -1e32f
#define BSD (BB*SS*DD)   /* 4194304 */

__device__ float g_scratch[(size_t)8 * BSD];

// ---------------- packed fp32x2 helpers ----------------
#define FMA2(c, a, b) asm("fma.rn.f32x2 %0, %1, %2, %0;" : "+l"(c) : "l"(a), "l"(b))
#define UNPK(lo, hi, p) asm("mov.b64 {%0,%1}, %2;" : "=f"(lo), "=f"(hi) : "l"(p))
__device__ __forceinline__ unsigned long long pk2(float lo, float hi) {
  unsigned long long r; asm("mov.b64 %0, {%1,%2};" : "=l"(r) : "f"(lo), "f"(hi)); return r;
}
__device__ __forceinline__ unsigned long long pk1(float v) { return pk2(v, v); }

// ---------------------------------------------------------------------------
// FMA2 GEMM core (R5, proven), parametrized by block coords (bx, by).
// ---------------------------------------------------------------------------
__device__ __forceinline__ void gemm2_body(
    const float* __restrict__ A, int lda,
    const float* __restrict__ W0, const float* __restrict__ W1,
    const float* __restrict__ bias0, const float* __restrict__ bias1,
    float* __restrict__ C0, float* __restrict__ C1, int K, int N1,
    int bx, int by,
    float (*As)[132], float (*Ws)[132])   // [2*8][132] each
{
  const int tid = threadIdx.x;
  const int tx = tid & 15, ty = tid >> 4;
  const int m0 = by * 128;
  const int n0g = bx * 128;
  const float* W; const float* bias; float* C; int n0;
  if (n0g < N1) { W = W0; bias = bias0; C = C0; n0 = n0g; }
  else          { W = W1; bias = bias1; C = C1; n0 = n0g - N1; }

  const int arow = tid >> 1, akq = (tid & 1) * 4;
  const int wkr = tid >> 5, wc4 = (tid & 31) * 4;
  const float* Aptr = A + (size_t)(m0 + arow)*lda + akq;
  const float* Wptr = W + (size_t)wkr*512 + n0 + wc4;

  unsigned long long acc[2][4][2][2];
  #pragma unroll
  for (int ih = 0; ih < 2; ih++)
    #pragma unroll
    for (int i = 0; i < 4; i++)
      #pragma unroll
      for (int jh = 0; jh < 2; jh++)
        { acc[ih][i][jh][0] = 0ull; acc[ih][i][jh][1] = 0ull; }

  {
    float4 va = *(const float4*)Aptr;
    float4 vw = *(const float4*)Wptr;
    As[0*8 + akq+0][arow] = va.x;
    As[0*8 + akq+1][arow] = va.y;
    As[0*8 + akq+2][arow] = va.z;
    As[0*8 + akq+3][arow] = va.w;
    *(float4*)&Ws[0*8 + wkr][wc4] = vw;
  }
  __syncthreads();

  const int nch = K >> 3;
  for (int c = 0; c < nch; c++) {
    int buf = c & 1;
    bool more = (c + 1) < nch;
    float4 na, nw;
    if (more) {
      na = *(const float4*)(Aptr + (c+1)*8);
      nw = *(const float4*)(Wptr + (size_t)(c+1)*8*512);
    }
    #pragma unroll
    for (int k = 0; k < 8; k++) {
      float4 a0 = *(const float4*)&As[buf*8 + k][ty*4];
      float4 a1 = *(const float4*)&As[buf*8 + k][64 + ty*4];
      float4 w0 = *(const float4*)&Ws[buf*8 + k][tx*4];
      float4 w1 = *(const float4*)&Ws[buf*8 + k][64 + tx*4];
      unsigned long long bp[2][2];
      bp[0][0] = pk2(w0.x, w0.y); bp[0][1] = pk2(w0.z, w0.w);
      bp[1][0] = pk2(w1.x, w1.y); bp[1][1] = pk2(w1.z, w1.w);
      unsigned long long ap[2][4];
      ap[0][0] = pk1(a0.x); ap[0][1] = pk1(a0.y); ap[0][2] = pk1(a0.z); ap[0][3] = pk1(a0.w);
      ap[1][0] = pk1(a1.x); ap[1][1] = pk1(a1.y); ap[1][2] = pk1(a1.z); ap[1][3] = pk1(a1.w);
      #pragma unroll
      for (int ih = 0; ih < 2; ih++)
        #pragma unroll
        for (int i = 0; i < 4; i++)
          #pragma unroll
          for (int jh = 0; jh < 2; jh++) {
            FMA2(acc[ih][i][jh][0], ap[ih][i], bp[jh][0]);
            FMA2(acc[ih][i][jh][1], ap[ih][i], bp[jh][1]);
          }
    }
    if (more) {
      int nb = buf ^ 1;
      As[nb*8 + akq+0][arow] = na.x;
      As[nb*8 + akq+1][arow] = na.y;
      As[nb*8 + akq+2][arow] = na.z;
      As[nb*8 + akq+3][arow] = na.w;
      *(float4*)&Ws[nb*8 + wkr][wc4] = nw;
      __syncthreads();
    }
  }

  #pragma unroll
  for (int ih = 0; ih < 2; ih++)
    #pragma unroll
    for (int i = 0; i < 4; i++) {
      int row = m0 + ih*64 + ty*4 + i;
      #pragma unroll
      for (int jh = 0; jh < 2; jh++) {
        int cn = n0 + jh*64 + tx*4;
        float4 o;
        UNPK(o.x, o.y, acc[ih][i][jh][0]);
        UNPK(o.z, o.w, acc[ih][i][jh][1]);
        o.x += bias[cn+0]; o.y += bias[cn+1]; o.z += bias[cn+2]; o.w += bias[cn+3];
        *(float4*)&C[(size_t)row*512 + cn] = o;
      }
    }
}

__global__ __launch_bounds__(256) void gemm2_kernel(
    const float* __restrict__ A, int lda,
    const float* __restrict__ W0, const float* __restrict__ W1,
    const float* __restrict__ bias0, const float* __restrict__ bias1,
    float* __restrict__ C0, float* __restrict__ C1, int K, int N1)
{
  __shared__ float As[16][132];
  __shared__ float Ws[16][132];
  gemm2_body(A, lda, W0, W1, bias0, bias1, C0, C1, K, N1,
             blockIdx.x, blockIdx.y, As, Ws);
}

// z-batched variant: blockIdx.z selects between two independent GEMM problems
__global__ __launch_bounds__(256) void gemm2z_kernel(
    const float* __restrict__ A0, const float* __restrict__ A1,
    const float* __restrict__ W00, const float* __restrict__ W01,
    const float* __restrict__ W10, const float* __restrict__ W11,
    const float* __restrict__ b00, const float* __restrict__ b01,
    const float* __restrict__ b10, const float* __restrict__ b11,
    float* __restrict__ C00, float* __restrict__ C01,
    float* __restrict__ C10, float* __restrict__ C11,
    int K, int N1)
{
  __shared__ float As[16][132];
  __shared__ float Ws[16][132];
  if (blockIdx.z == 0)
    gemm2_body(A0, 512, W00, W01, b00, b01, C00, C01, K, N1,
               blockIdx.x, blockIdx.y, As, Ws);
  else
    gemm2_body(A1, 512, W10, W11, b10, b11, C10, C11, K, N1,
               blockIdx.x, blockIdx.y, As, Ws);
}

// 3-segment GEMM: seg = blockIdx.x>>2 in {0,1,2}
__global__ __launch_bounds__(256) void gemm_seg3_kernel(
    const float* __restrict__ A01, const float* __restrict__ A2,
    const float* __restrict__ Wg0, const float* __restrict__ bg0, float* __restrict__ Cg0,
    const float* __restrict__ Wg1, const float* __restrict__ bg1, float* __restrict__ Cg1,
    const float* __restrict__ Wg2, const float* __restrict__ bg2, float* __restrict__ Cg2)
{
  __shared__ float As[16][132];
  __shared__ float Ws[16][132];
  int seg = blockIdx.x >> 2;
  int bx = blockIdx.x & 3;
  const float* A = (seg == 2) ? A2 : A01;
  const float* W = (seg == 0) ? Wg0 : (seg == 1) ? Wg1 : Wg2;
  const float* bs = (seg == 0) ? bg0 : (seg == 1) ? bg1 : bg2;
  float* C = (seg == 0) ? Cg0 : (seg == 1) ? Cg1 : Cg2;
  gemm2_body(A, 512, W, W, bs, bs, C, C, 512, 512, bx, blockIdx.y, As, Ws);
}

// ---------------------------------------------------------------------------
// Causal attention — EXACT R13 proven core (2875.9us run).
// ---------------------------------------------------------------------------
template<int MODE>
__device__ __forceinline__ bool msk2(int gi, int j) {
  return (MODE == 0) ? (j <= gi) : (j < gi);
}

template<int MODE, int MAXOUT>
__global__ __launch_bounds__(256) void attn2_kernel(
    const float* __restrict__ qk0, const float* __restrict__ v0,
    float* __restrict__ out0,
    const float* __restrict__ qk1, const float* __restrict__ v1,
    float* __restrict__ out1,
    const float* __restrict__ gamma)
{
  extern __shared__ float sm[];
  float* srow  = sm;                    // 32 * 1024
  float* qs    = srow + 32*SS;          // 32 * 68
  float* ks    = qs + 32*68;            // 128 * 68 (K tile, reused for V)
  float* csumA = ks + 128*68;           // 8 warps * 4 rows * 32

  int i0 = blockIdx.x * 32;
  int h  = blockIdx.y;
  int zz = blockIdx.z;
  int strm = zz >> 3;
  int b  = zz & 7;
  const float* qk = strm ? qk1 : qk0;
  const float* v  = strm ? v1  : v0;
  float* out      = strm ? out1 : out0;
  const float* gm = gamma + strm*HH;

  int tid = threadIdx.x;
  int lane = tid & 31, wi = tid >> 5;
  int tj = lane;
  const float* qbase = qk + (size_t)b*SS*DD + h*DKK;
  const float* vbase = v  + (size_t)b*SS*DD + h*DKK;
  int jlim = i0 + 32;

  for (int idx = tid; idx < 32*16; idx += 256) {
    int i = idx >> 4, dc = (idx & 15) << 2;
    *(float4*)&qs[i*68 + dc] = *(const float4*)&qbase[(size_t)(i0 + i)*DD + dc];
  }

  // ---- phase 1: scores ----
  for (int j0 = 0; j0 < jlim; j0 += 128) {
    __syncthreads();
    for (int idx = tid; idx < 128*16; idx += 256) {
      int rj = idx >> 4, dc = (idx & 15) << 2;
      *(float4*)&ks[rj*68 + dc] = *(const float4*)&qbase[(size_t)(j0 + rj)*DD + dc];
    }
    __syncthreads();
    float acc[4][4] = {};
    #pragma unroll
    for (int d4 = 0; d4 < 16; d4++) {
      float4 kf[4];
      #pragma unroll
      for (int u = 0; u < 4; u++)
        kf[u] = *(const float4*)&ks[(tj + 32*u)*68 + d4*4];
      #pragma unroll
      for (int r = 0; r < 4; r++) {
        float4 qf = *(const float4*)&qs[(wi*4 + r)*68 + d4*4];
        #pragma unroll
        for (int u = 0; u < 4; u++) {
          acc[r][u] = fmaf(qf.x, kf[u].x, acc[r][u]);
          acc[r][u] = fmaf(qf.y, kf[u].y, acc[r][u]);
          acc[r][u] = fmaf(qf.z, kf[u].z, acc[r][u]);
          acc[r][u] = fmaf(qf.w, kf[u].w, acc[r][u]);
        }
      }
    }
    #pragma unroll
    for (int r = 0; r < 4; r++) {
      int gi = i0 + wi*4 + r;
      #pragma unroll
      for (int u = 0; u < 4; u++) {
        int j = j0 + tj + 32*u;
        srow[(wi*4 + r)*SS + j] = msk2<MODE>(gi, j) ? acc[r][u]*0.125f : NEGV;
      }
    }
  }
  __syncwarp();

  // ---- phase 2: 4-row-interleaved softmax -> cumsum -> decay -> softmax ----
  float gmv = -fabsf(gm[h]);
  int nc = blockIdx.x + 1;                 // 32-col chunks
  float* csums = csumA + wi*128;           // [4][32]
  float* rows[4];
  #pragma unroll
  for (int r = 0; r < 4; r++) rows[r] = srow + (wi*4 + r)*SS;
  const int gib = i0 + wi*4;

  float mx[4] = {-INFINITY, -INFINITY, -INFINITY, -INFINITY};
  for (int c = 0; c < nc; c++) {
    int j = c*32 + lane;
    #pragma unroll
    for (int r = 0; r < 4; r++) mx[r] = fmaxf(mx[r], rows[r][j]);
  }
  #pragma unroll
  for (int o = 16; o; o >>= 1)
    #pragma unroll
    for (int r = 0; r < 4; r++) mx[r] = fmaxf(mx[r], __shfl_xor_sync(0xffffffffu, mx[r], o));

  for (int c = 0; c < nc; c++) {
    int j = c*32 + lane;
    float t[4];
    #pragma unroll
    for (int r = 0; r < 4; r++) t[r] = __expf(rows[r][j] - mx[r]);
    #pragma unroll
    for (int o = 16; o; o >>= 1)
      #pragma unroll
      for (int r = 0; r < 4; r++) t[r] += __shfl_xor_sync(0xffffffffu, t[r], o);
    if (lane == 0) {
      #pragma unroll
      for (int r = 0; r < 4; r++) csums[r*32 + c] = t[r];
    }
  }
  __syncwarp();

  float csv[4], incl[4], base[4], invz[4];
  #pragma unroll
  for (int r = 0; r < 4; r++) { csv[r] = (lane < nc) ? csums[r*32 + lane] : 0.f; incl[r] = csv[r]; }
  #pragma unroll
  for (int o = 1; o < 32; o <<= 1)
    #pragma unroll
    for (int r = 0; r < 4; r++) {
      float t = __shfl_up_sync(0xffffffffu, incl[r], o);
      if (lane >= o) incl[r] += t;
    }
  #pragma unroll
  for (int r = 0; r < 4; r++) {
    float z = __shfl_sync(0xffffffffu, incl[r], 31);
    base[r] = incl[r] - csv[r];
    invz[r] = __fdividef(1.f, z);
  }

  float m2[4] = {-INFINITY, -INFINITY, -INFINITY, -INFINITY};
  for (int c = 0; c < nc; c++) {
    int j = c*32 + lane;
    float sv[4], e[4];
    #pragma unroll
    for (int r = 0; r < 4; r++) { sv[r] = rows[r][j]; e[r] = __expf(sv[r] - mx[r]); }
    #pragma unroll
    for (int o = 1; o < 32; o <<= 1)
      #pragma unroll
      for (int r = 0; r < 4; r++) {
        float t = __shfl_up_sync(0xffffffffu, e[r], o);
        if (lane >= o) e[r] += t;
      }
    #pragma unroll
    for (int r = 0; r < 4; r++) {
      float cum = (__shfl_sync(0xffffffffu, base[r], c) + e[r]) * invz[r];
      float rem = 1.f - cum;
      float pos = fabsf((float)(gib + r - j));
      float dist = sqrtf(fmaxf(rem * pos, 0.f));
      float dec = fminf(fmaxf(__expf(dist * gmv), 1e-5f), 1e5f);
      float s2 = msk2<MODE>(gib + r, j) ? sv[r] * dec : NEGV;
      rows[r][j] = s2;
      m2[r] = fmaxf(m2[r], s2);
    }
  }
  #pragma unroll
  for (int o = 16; o; o >>= 1)
    #pragma unroll
    for (int r = 0; r < 4; r++) m2[r] = fmaxf(m2[r], __shfl_xor_sync(0xffffffffu, m2[r], o));

  float z2[4] = {0.f, 0.f, 0.f, 0.f};
  for (int c = 0; c < nc; c++) {
    int j = c*32 + lane;
    #pragma unroll
    for (int r = 0; r < 4; r++) {
      float e2 = __expf(rows[r][j] - m2[r]);
      rows[r][j] = e2; z2[r] += e2;
    }
  }
  #pragma unroll
  for (int o = 16; o; o >>= 1)
    #pragma unroll
    for (int r = 0; r < 4; r++) z2[r] += __shfl_xor_sync(0xffffffffu, z2[r], o);
  float scl[4];
  #pragma unroll
  for (int r = 0; r < 4; r++) {
    scl[r] = __fdividef(1.f, z2[r]);
    if (MAXOUT) scl[r] *= fminf(z2[r], 5.f);
  }
  for (int c = 0; c < nc; c++) {
    int j = c*32 + lane;
    #pragma unroll
    for (int r = 0; r < 4; r++)
      rows[r][j] = msk2<MODE>(gib + r, j) ? rows[r][j]*scl[r] : 0.f;
  }

  // ---- phase 3: out = A @ V ----
  float oa[4][2] = {};
  int d0 = 2*lane;
  for (int j0 = 0; j0 < jlim; j0 += 128) {
    __syncthreads();
    for (int idx = tid; idx < 128*16; idx += 256) {
      int rj = idx >> 4, dc = (idx & 15) << 2;
      *(float4*)&ks[rj*68 + dc] = *(const float4*)&vbase[(size_t)(j0 + rj)*DD + dc];
    }
    __syncthreads();
    int lim = jlim - j0; if (lim > 128) lim = 128;
    for (int jq = 0; jq < lim; jq += 4) {
      float4 af[4];
      #pragma unroll
      for (int r = 0; r < 4; r++)
        af[r] = *(const float4*)&srow[(wi*4 + r)*SS + j0 + jq];
      #pragma unroll
      for (int u = 0; u < 4; u++) {
        float2 vv = *(const float2*)&ks[(jq + u)*68 + d0];
        #pragma unroll
        for (int r = 0; r < 4; r++) {
          float a = (u == 0) ? af[r].x : (u == 1) ? af[r].y : (u == 2) ? af[r].z : af[r].w;
          oa[r][0] = fmaf(a, vv.x, oa[r][0]);
          oa[r][1] = fmaf(a, vv.y, oa[r][1]);
        }
      }
    }
  }
  #pragma unroll
  for (int r = 0; r < 4; r++) {
    float2 st; st.x = oa[r][0]; st.y = oa[r][1];
    *(float2*)&out[((size_t)b*SS + i0 + wi*4 + r)*DD + h*DKK + d0] = st;
  }
}

// ---------------------------------------------------------------------------
// Window attention (19 cols), one warp per (b,h,i)
// ---------------------------------------------------------------------------
__global__ __launch_bounds__(256) void win_kernel(
    const float* __restrict__ qw, const float* __restrict__ v,
    float* __restrict__ out, const float* __restrict__ gamma)
{
  int i = blockIdx.x;
  int b = blockIdx.y;
  int h = threadIdx.x >> 5;
  int lane = threadIdx.x & 31;
  const float* qbase = qw + (size_t)b*SS*DD + h*DKK;
  const float* vbase = v  + (size_t)b*SS*DD + h*DKK;
  float* obase = out + ((size_t)b*SS + i)*DD + h*DKK;
  int d0 = 2*lane;

  int wstart = i - 19; if (wstart < 0) wstart = 0;
  int n = i - wstart;
  if (n == 0) {
    float2 zz; zz.x = 0.f; zz.y = 0.f;
    *(float2*)(obase + d0) = zz;
    return;
  }
  bool act = lane < n;
  int j = wstart + lane;

  float s = NEGV;
  if (act) {
    const float4* q4 = (const float4*)(qbase + (size_t)i*DD);
    const float4* k4 = (const float4*)(qbase + (size_t)j*DD);
    float acc = 0.f;
    #pragma unroll
    for (int d4 = 0; d4 < 16; d4++) {
      float4 qa = q4[d4], kv = k4[d4];
      acc = fmaf(qa.x, kv.x, acc);
      acc = fmaf(qa.y, kv.y, acc);
      acc = fmaf(qa.z, kv.z, acc);
      acc = fmaf(qa.w, kv.w, acc);
    }
    s = acc * 0.125f;
  }
  float m = s;
  #pragma unroll
  for (int o = 16; o; o >>= 1) m = fmaxf(m, __shfl_xor_sync(0xffffffffu, m, o));
  float e = __expf(s - m);
  float incl = e;
  #pragma unroll
  for (int o = 1; o < 32; o <<= 1) {
    float t = __shfl_up_sync(0xffffffffu, incl, o);
    if (lane >= o) incl += t;
  }
  float z = __shfl_sync(0xffffffffu, incl, 31);
  float cum = incl * __fdividef(1.f, z);
  float rem = 1.f - cum;
  float pos = fabsf((float)(i - j));
  float dist = sqrtf(fmaxf(rem * pos, 0.f));
  float gmv = -fabsf(gamma[h]);
  float dec = fminf(fmaxf(__expf(dist * gmv), 1e-5f), 1e5f);
  float s2 = act ? s * dec : NEGV;
  float m2 = s2;
  #pragma unroll
  for (int o = 16; o; o >>= 1) m2 = fmaxf(m2, __shfl_xor_sync(0xffffffffu, m2, o));
  float e2 = __expf(s2 - m2);
  float z2 = e2;
  #pragma unroll
  for (int o = 16; o; o >>= 1) z2 += __shfl_xor_sync(0xffffffffu, z2, o);
  float a = act ? e2 * __fdividef(1.f, z2) : 0.f;

  float o0 = 0.f, o1 = 0.f;
  for (int jj = 0; jj < n; jj++) {
    float aj = __shfl_sync(0xffffffffu, a, jj);
    float2 vv = *(const float2*)(vbase + (size_t)(wstart + jj)*DD + d0);
    o0 = fmaf(aj, vv.x, o0);
    o1 = fmaf(aj, vv.y, o1);
  }
  float2 st; st.x = o0; st.y = o1;
  *(float2*)(obase + d0) = st;
}

// ---------------------------------------------------------------------------
// LayerNorm(x + y), z-batched over two independent problems (blockIdx.y)
// ---------------------------------------------------------------------------
__global__ __launch_bounds__(128) void ln_res_z_kernel(
    const float* __restrict__ x0, const float* __restrict__ y0,
    const float* __restrict__ lw0, const float* __restrict__ lb0,
    float* __restrict__ o0,
    const float* __restrict__ x1, const float* __restrict__ y1,
    const float* __restrict__ lw1, const float* __restrict__ lb1,
    float* __restrict__ o1)
{
  __shared__ float sb1[4], sb2[4];
  size_t row = blockIdx.x;
  const float* x; const float* y; const float* lw; const float* lb; float* out;
  if (blockIdx.y == 0) { x = x0; y = y0; lw = lw0; lb = lb0; out = o0; }
  else                 { x = x1; y = y1; lw = lw1; lb = lb1; out = o1; }
  const float* xr = x + row*DD;
  const float* yr = y + row*DD;
  int tid = threadIdx.x, lane = tid & 31, w = tid >> 5;
  float v[4]; float s = 0.f, q = 0.f;
  #pragma unroll
  for (int u = 0; u < 4; u++) {
    int c = tid + u*128;
    float t = xr[c] + yr[c];
    v[u] = t; s += t; q += t*t;
  }
  #pragma unroll
  for (int o = 16; o; o >>= 1) { s += __shfl_xor_sync(0xffffffffu, s, o); q += __shfl_xor_sync(0xffffffffu, q, o); }
  if (lane == 0) { sb1[w] = s; sb2[w] = q; }
  __syncthreads();
  s = sb1[0]+sb1[1]+sb1[2]+sb1[3];
  q = sb2[0]+sb2[1]+sb2[2]+sb2[3];
  float mu = s * (1.f/DD);
  float var = q * (1.f/DD) - mu*mu;
  float rs = rsqrtf(var + 1e-5f);
  #pragma unroll
  for (int u = 0; u < 4; u++) {
    int c = tid + u*128;
    out[row*DD + c] = (v[u]-mu)*rs*lw[c] + lb[c];
  }
}

// ---------------------------------------------------------------------------
// X[:, :512] = LN(hq+o), X[:, 512:] = LN(hq+o+ow)   (X has ld 1024)
// ---------------------------------------------------------------------------
__global__ __launch_bounds__(128) void fuse3_kernel(
    const float* __restrict__ hq, const float* __restrict__ o,
    const float* __restrict__ ow,
    const float* __restrict__ lw, const float* __restrict__ lb,
    float* __restrict__ X)
{
  __shared__ float sbuf[4][4];
  size_t row = blockIdx.x;
  int tid = threadIdx.x, lane = tid & 31, w = tid >> 5;
  const float* hr = hq + row*DD;
  const float* orr = o + row*DD;
  const float* owr = ow + row*DD;
  float v1[4], v2[4]; float st[4] = {0.f,0.f,0.f,0.f};
  #pragma unroll
  for (int u = 0; u < 4; u++) {
    int c = tid + u*128;
    float a  = hr[c] + orr[c];
    float b2 = a + owr[c];
    v1[u] = a; v2[u] = b2;
    st[0] += a;  st[1] += a*a;
    st[2] += b2; st[3] += b2*b2;
  }
  #pragma unroll
  for (int k = 0; k < 4; k++)
    #pragma unroll
    for (int o2 = 16; o2; o2 >>= 1) st[k] += __shfl_xor_sync(0xffffffffu, st[k], o2);
  if (lane == 0) { sbuf[0][w]=st[0]; sbuf[1][w]=st[1]; sbuf[2][w]=st[2]; sbuf[3][w]=st[3]; }
  __syncthreads();
  #pragma unroll
  for (int k = 0; k < 4; k++) st[k] = sbuf[k][0]+sbuf[k][1]+sbuf[k][2]+sbuf[k][3];
  float mu1 = st[0]*(1.f/DD), var1 = st[1]*(1.f/DD) - mu1*mu1;
  float mu2 = st[2]*(1.f/DD), var2 = st[3]*(1.f/DD) - mu2*mu2;
  float rs1 = rsqrtf(var1 + 1e-5f);
  float rs2 = rsqrtf(var2 + 1e-5f);
  #pragma unroll
  for (int u = 0; u < 4; u++) {
    int c = tid + u*128;
    X[row*1024 + c]       = (v1[u]-mu1)*rs1*lw[c] + lb[c];
    X[row*1024 + 512 + c] = (v2[u]-mu2)*rs2*lw[c] + lb[c];
  }
}

// ---------------------------------------------------------------------------
extern "C" void kernel_launch(void* const* d_in, const int* in_sizes, int n_in,
                              void* d_out, int out_size)
{
  const float* q_emb  = (const float*)d_in[0];
  const float* s_emb  = (const float*)d_in[1];
  const float* Wq     = (const float*)d_in[2];
  const float* bq     = (const float*)d_in[3];
  const float* Wqw    = (const float*)d_in[4];
  const float* bqw    = (const float*)d_in[5];
  const float* Wv     = (const float*)d_in[6];
  const float* bv     = (const float*)d_in[7];
  const float* Wo     = (const float*)d_in[8];
  const float* bo     = (const float*)d_in[9];
  const float* Wow    = (const float*)d_in[10];
  const float* bow    = (const float*)d_in[11];
  const float* gammas = (const float*)d_in[12];
  const float* ln_w   = (const float*)d_in[13];
  const float* ln_b   = (const float*)d_in[14];
  const float* Wc     = (const float*)d_in[15];
  const float* bc     = (const float*)d_in[16];
  float* outp = (float*)d_out;

  float* scratch = nullptr;
  cudaGetSymbolAddress((void**)&scratch, g_scratch);
  float* t0 = scratch;
  float* t1 = scratch + 1*(size_t)BSD;
  float* t2 = scratch + 2*(size_t)BSD;
  float* t3 = scratch + 3*(size_t)BSD;
  float* t4 = scratch + 4*(size_t)BSD;
  float* t5 = scratch + 5*(size_t)BSD;
  float* s6 = scratch + 6*(size_t)BSD;
  float* s7 = scratch + 7*(size_t)BSD;
  float* X  = t4;                        // [8192,1024] spans t4..t5 (used in tail)
  float* hqo = outp + (size_t)BSD;
  float* hso = outp + 2*(size_t)BSD;

  const int SMEM_ATTN = (32*SS + 32*68 + 128*68 + 8*128) * (int)sizeof(float); // 178688 B
  cudaFuncSetAttribute(attn2_kernel<0,0>, cudaFuncAttributeMaxDynamicSharedMemorySize, SMEM_ATTN);
  cudaFuncSetAttribute(attn2_kernel<1,1>, cudaFuncAttributeMaxDynamicSharedMemorySize, SMEM_ATTN);

  dim3 gdualz(8, 64, 2), gsingz(4, 64, 2);
  dim3 gseg3(12, 64);
  dim3 gsing(4, 64);
  dim3 gaz(SS/32, HH, 2*BB);
  dim3 ga1(SS/32, HH, BB);
  dim3 gw(SS, BB);
  dim3 glnz(BB*SS, 2);
  size_t DDl = (size_t)DD*DD;

  cudaStream_t s2str;
  cudaStreamCreateWithFlags(&s2str, cudaStreamNonBlocking);
  cudaEvent_t evA, evB;
  cudaEventCreateWithFlags(&evA, cudaEventDisableTiming);
  cudaEventCreateWithFlags(&evB, cudaEventDisableTiming);

  // ---- blocks 1+2 merged (independent streams via z-batching) ----
  gemm2z_kernel<<<gdualz, 256>>>(q_emb, s_emb,
                                 Wq, Wv, Wq + DDl, Wv + DDl,
                                 bq, bv, bq + DD, bv + DD,
                                 t0, t1, s6, s7, 512, 512);
  attn2_kernel<0,0><<<gaz, 256, SMEM_ATTN>>>(t0, t1, t2, s6, s7, t4, gammas);
  gemm2z_kernel<<<gsingz, 256>>>(t2, t4,
                                 Wo, Wo, Wo + DDl, Wo + DDl,
                                 bo, bo, bo + DD, bo + DD,
                                 t3, t3, t5, t5, 512, 512);
  ln_res_z_kernel<<<glnz, 128>>>(q_emb, t3, ln_w, ln_b, hqo,
                                 s_emb, t5, ln_w + DD, ln_b + DD, hso);

  // ---- block 3 ----
  gemm_seg3_kernel<<<gseg3, 256>>>(hqo, hso,
                                   Wq + 2*DDl, bq + 2*DD, t0,
                                   Wqw + 2*DDl, bqw + 2*DD, s6,
                                   Wv + 2*DDl, bv + 2*DD, t1);
  // fork: win (no smem, tiny blocks) runs concurrently with the big attn launch
  cudaEventRecord(evA, 0);
  cudaStreamWaitEvent(s2str, evA, 0);
  win_kernel<<<gw, 256, 0, s2str>>>(s6, t1, t4, gammas + 2*HH);
  cudaEventRecord(evB, s2str);
  attn2_kernel<1,1><<<ga1, 256, SMEM_ATTN>>>(t0, t1, t2, t0, t1, t2, gammas + 2*HH);
  cudaStreamWaitEvent(0, evB, 0);   // join before o/ow GEMM (needs t4)
  gemm2z_kernel<<<gsingz, 256>>>(t2, t4,
                                 Wo + 2*DDl, Wo + 2*DDl, Wow, Wow,
                                 bo + 2*DD, bo + 2*DD, bow, bow,
                                 t3, t3, t0, t0, 512, 512);

  // ---- X = [LN(hq+o) | LN(hq+o+ow)] ; out = X @ Wc + bc ----
  fuse3_kernel<<<BB*SS, 128>>>(hqo, t3, t0, ln_w + 2*DD, ln_b + 2*DD, X);
  gemm2_kernel<<<gsing, 256>>>(X, 1024, Wc, Wc, bc, bc, outp, outp, 1024, 512);

  cudaEventDestroy(evA);
  cudaEventDestroy(evB);
  cudaStreamDestroy(s2str);
}

// round 17
// speedup vs baseline: 1.0248x; 1.0055x over previous
#include <cuda_runtime.h>
#include <cuda_bf16.h>
#include <math.h>

#define BB 8
#define SS 1024
#define DD 512
#define HH 8
#define DKK 64
#define NEGV -1e32f
#define BSD (BB*SS*DD)   /* 4194304 */

__device__ float g_scratch[(size_t)8 * BSD];

// ---------------- packed fp32x2 helpers ----------------
#define FMA2(c, a, b) asm("fma.rn.f32x2 %0, %1, %2, %0;" : "+l"(c) : "l"(a), "l"(b))
#define UNPK(lo, hi, p) asm("mov.b64 {%0,%1}, %2;" : "=f"(lo), "=f"(hi) : "l"(p))
__device__ __forceinline__ unsigned long long pk2(float lo, float hi) {
  unsigned long long r; asm("mov.b64 %0, {%1,%2};" : "=l"(r) : "f"(lo), "f"(hi)); return r;
}
__device__ __forceinline__ unsigned long long pk1(float v) { return pk2(v, v); }

// ---------------------------------------------------------------------------
// FMA2 GEMM core (R5, proven), parametrized by block coords (bx, by).
// ---------------------------------------------------------------------------
__device__ __forceinline__ void gemm2_body(
    const float* __restrict__ A, int lda,
    const float* __restrict__ W0, const float* __restrict__ W1,
    const float* __restrict__ bias0, const float* __restrict__ bias1,
    float* __restrict__ C0, float* __restrict__ C1, int K, int N1,
    int bx, int by,
    float (*As)[132], float (*Ws)[132])   // [2*8][132] each
{
  const int tid = threadIdx.x;
  const int tx = tid & 15, ty = tid >> 4;
  const int m0 = by * 128;
  const int n0g = bx * 128;
  const float* W; const float* bias; float* C; int n0;
  if (n0g < N1) { W = W0; bias = bias0; C = C0; n0 = n0g; }
  else          { W = W1; bias = bias1; C = C1; n0 = n0g - N1; }

  const int arow = tid >> 1, akq = (tid & 1) * 4;
  const int wkr = tid >> 5, wc4 = (tid & 31) * 4;
  const float* Aptr = A + (size_t)(m0 + arow)*lda + akq;
  const float* Wptr = W + (size_t)wkr*512 + n0 + wc4;

  unsigned long long acc[2][4][2][2];
  #pragma unroll
  for (int ih = 0; ih < 2; ih++)
    #pragma unroll
    for (int i = 0; i < 4; i++)
      #pragma unroll
      for (int jh = 0; jh < 2; jh++)
        { acc[ih][i][jh][0] = 0ull; acc[ih][i][jh][1] = 0ull; }

  {
    float4 va = *(const float4*)Aptr;
    float4 vw = *(const float4*)Wptr;
    As[0*8 + akq+0][arow] = va.x;
    As[0*8 + akq+1][arow] = va.y;
    As[0*8 + akq+2][arow] = va.z;
    As[0*8 + akq+3][arow] = va.w;
    *(float4*)&Ws[0*8 + wkr][wc4] = vw;
  }
  __syncthreads();

  const int nch = K >> 3;
  for (int c = 0; c < nch; c++) {
    int buf = c & 1;
    bool more = (c + 1) < nch;
    float4 na, nw;
    if (more) {
      na = *(const float4*)(Aptr + (c+1)*8);
      nw = *(const float4*)(Wptr + (size_t)(c+1)*8*512);
    }
    #pragma unroll
    for (int k = 0; k < 8; k++) {
      float4 a0 = *(const float4*)&As[buf*8 + k][ty*4];
      float4 a1 = *(const float4*)&As[buf*8 + k][64 + ty*4];
      float4 w0 = *(const float4*)&Ws[buf*8 + k][tx*4];
      float4 w1 = *(const float4*)&Ws[buf*8 + k][64 + tx*4];
      unsigned long long bp[2][2];
      bp[0][0] = pk2(w0.x, w0.y); bp[0][1] = pk2(w0.z, w0.w);
      bp[1][0] = pk2(w1.x, w1.y); bp[1][1] = pk2(w1.z, w1.w);
      unsigned long long ap[2][4];
      ap[0][0] = pk1(a0.x); ap[0][1] = pk1(a0.y); ap[0][2] = pk1(a0.z); ap[0][3] = pk1(a0.w);
      ap[1][0] = pk1(a1.x); ap[1][1] = pk1(a1.y); ap[1][2] = pk1(a1.z); ap[1][3] = pk1(a1.w);
      #pragma unroll
      for (int ih = 0; ih < 2; ih++)
        #pragma unroll
        for (int i = 0; i < 4; i++)
          #pragma unroll
          for (int jh = 0; jh < 2; jh++) {
            FMA2(acc[ih][i][jh][0], ap[ih][i], bp[jh][0]);
            FMA2(acc[ih][i][jh][1], ap[ih][i], bp[jh][1]);
          }
    }
    if (more) {
      int nb = buf ^ 1;
      As[nb*8 + akq+0][arow] = na.x;
      As[nb*8 + akq+1][arow] = na.y;
      As[nb*8 + akq+2][arow] = na.z;
      As[nb*8 + akq+3][arow] = na.w;
      *(float4*)&Ws[nb*8 + wkr][wc4] = nw;
      __syncthreads();
    }
  }

  #pragma unroll
  for (int ih = 0; ih < 2; ih++)
    #pragma unroll
    for (int i = 0; i < 4; i++) {
      int row = m0 + ih*64 + ty*4 + i;
      #pragma unroll
      for (int jh = 0; jh < 2; jh++) {
        int cn = n0 + jh*64 + tx*4;
        float4 o;
        UNPK(o.x, o.y, acc[ih][i][jh][0]);
        UNPK(o.z, o.w, acc[ih][i][jh][1]);
        o.x += bias[cn+0]; o.y += bias[cn+1]; o.z += bias[cn+2]; o.w += bias[cn+3];
        *(float4*)&C[(size_t)row*512 + cn] = o;
      }
    }
}

__global__ __launch_bounds__(256) void gemm2_kernel(
    const float* __restrict__ A, int lda,
    const float* __restrict__ W0, const float* __restrict__ W1,
    const float* __restrict__ bias0, const float* __restrict__ bias1,
    float* __restrict__ C0, float* __restrict__ C1, int K, int N1)
{
  __shared__ float As[16][132];
  __shared__ float Ws[16][132];
  gemm2_body(A, lda, W0, W1, bias0, bias1, C0, C1, K, N1,
             blockIdx.x, blockIdx.y, As, Ws);
}

// z-batched variant: blockIdx.z selects between two independent GEMM problems
__global__ __launch_bounds__(256) void gemm2z_kernel(
    const float* __restrict__ A0, const float* __restrict__ A1,
    const float* __restrict__ W00, const float* __restrict__ W01,
    const float* __restrict__ W10, const float* __restrict__ W11,
    const float* __restrict__ b00, const float* __restrict__ b01,
    const float* __restrict__ b10, const float* __restrict__ b11,
    float* __restrict__ C00, float* __restrict__ C01,
    float* __restrict__ C10, float* __restrict__ C11,
    int K, int N1)
{
  __shared__ float As[16][132];
  __shared__ float Ws[16][132];
  if (blockIdx.z == 0)
    gemm2_body(A0, 512, W00, W01, b00, b01, C00, C01, K, N1,
               blockIdx.x, blockIdx.y, As, Ws);
  else
    gemm2_body(A1, 512, W10, W11, b10, b11, C10, C11, K, N1,
               blockIdx.x, blockIdx.y, As, Ws);
}

// 3-segment GEMM: seg = blockIdx.x>>2 in {0,1,2}
__global__ __launch_bounds__(256) void gemm_seg3_kernel(
    const float* __restrict__ A01, const float* __restrict__ A2,
    const float* __restrict__ Wg0, const float* __restrict__ bg0, float* __restrict__ Cg0,
    const float* __restrict__ Wg1, const float* __restrict__ bg1, float* __restrict__ Cg1,
    const float* __restrict__ Wg2, const float* __restrict__ bg2, float* __restrict__ Cg2)
{
  __shared__ float As[16][132];
  __shared__ float Ws[16][132];
  int seg = blockIdx.x >> 2;
  int bx = blockIdx.x & 3;
  const float* A = (seg == 2) ? A2 : A01;
  const float* W = (seg == 0) ? Wg0 : (seg == 1) ? Wg1 : Wg2;
  const float* bs = (seg == 0) ? bg0 : (seg == 1) ? bg1 : bg2;
  float* C = (seg == 0) ? Cg0 : (seg == 1) ? Cg1 : Cg2;
  gemm2_body(A, 512, W, W, bs, bs, C, C, 512, 512, bx, blockIdx.y, As, Ws);
}

// ---------------------------------------------------------------------------
// Causal attention — R13/R16 proven core; single change: final masked-rescale
// sweep (pass 5) removed, scale folded into phase-3 store. Masked entries are
// exactly 0 after pass 4 (exp underflow); fully-masked strict row gets scl=0.
// ---------------------------------------------------------------------------
template<int MODE>
__device__ __forceinline__ bool msk2(int gi, int j) {
  return (MODE == 0) ? (j <= gi) : (j < gi);
}

template<int MODE, int MAXOUT>
__global__ __launch_bounds__(256) void attn2_kernel(
    const float* __restrict__ qk0, const float* __restrict__ v0,
    float* __restrict__ out0,
    const float* __restrict__ qk1, const float* __restrict__ v1,
    float* __restrict__ out1,
    const float* __restrict__ gamma)
{
  extern __shared__ float sm[];
  float* srow  = sm;                    // 32 * 1024
  float* qs    = srow + 32*SS;          // 32 * 68
  float* ks    = qs + 32*68;            // 128 * 68 (K tile, reused for V)
  float* csumA = ks + 128*68;           // 8 warps * 4 rows * 32

  int i0 = blockIdx.x * 32;
  int h  = blockIdx.y;
  int zz = blockIdx.z;
  int strm = zz >> 3;
  int b  = zz & 7;
  const float* qk = strm ? qk1 : qk0;
  const float* v  = strm ? v1  : v0;
  float* out      = strm ? out1 : out0;
  const float* gm = gamma + strm*HH;

  int tid = threadIdx.x;
  int lane = tid & 31, wi = tid >> 5;
  int tj = lane;
  const float* qbase = qk + (size_t)b*SS*DD + h*DKK;
  const float* vbase = v  + (size_t)b*SS*DD + h*DKK;
  int jlim = i0 + 32;

  for (int idx = tid; idx < 32*16; idx += 256) {
    int i = idx >> 4, dc = (idx & 15) << 2;
    *(float4*)&qs[i*68 + dc] = *(const float4*)&qbase[(size_t)(i0 + i)*DD + dc];
  }

  // ---- phase 1: scores ----
  for (int j0 = 0; j0 < jlim; j0 += 128) {
    __syncthreads();
    for (int idx = tid; idx < 128*16; idx += 256) {
      int rj = idx >> 4, dc = (idx & 15) << 2;
      *(float4*)&ks[rj*68 + dc] = *(const float4*)&qbase[(size_t)(j0 + rj)*DD + dc];
    }
    __syncthreads();
    float acc[4][4] = {};
    #pragma unroll
    for (int d4 = 0; d4 < 16; d4++) {
      float4 kf[4];
      #pragma unroll
      for (int u = 0; u < 4; u++)
        kf[u] = *(const float4*)&ks[(tj + 32*u)*68 + d4*4];
      #pragma unroll
      for (int r = 0; r < 4; r++) {
        float4 qf = *(const float4*)&qs[(wi*4 + r)*68 + d4*4];
        #pragma unroll
        for (int u = 0; u < 4; u++) {
          acc[r][u] = fmaf(qf.x, kf[u].x, acc[r][u]);
          acc[r][u] = fmaf(qf.y, kf[u].y, acc[r][u]);
          acc[r][u] = fmaf(qf.z, kf[u].z, acc[r][u]);
          acc[r][u] = fmaf(qf.w, kf[u].w, acc[r][u]);
        }
      }
    }
    #pragma unroll
    for (int r = 0; r < 4; r++) {
      int gi = i0 + wi*4 + r;
      #pragma unroll
      for (int u = 0; u < 4; u++) {
        int j = j0 + tj + 32*u;
        srow[(wi*4 + r)*SS + j] = msk2<MODE>(gi, j) ? acc[r][u]*0.125f : NEGV;
      }
    }
  }
  __syncwarp();

  // ---- phase 2: 4-row-interleaved softmax -> cumsum -> decay -> softmax ----
  float gmv = -fabsf(gm[h]);
  int nc = blockIdx.x + 1;                 // 32-col chunks
  float* csums = csumA + wi*128;           // [4][32]
  float* rows[4];
  #pragma unroll
  for (int r = 0; r < 4; r++) rows[r] = srow + (wi*4 + r)*SS;
  const int gib = i0 + wi*4;

  float mx[4] = {-INFINITY, -INFINITY, -INFINITY, -INFINITY};
  for (int c = 0; c < nc; c++) {
    int j = c*32 + lane;
    #pragma unroll
    for (int r = 0; r < 4; r++) mx[r] = fmaxf(mx[r], rows[r][j]);
  }
  #pragma unroll
  for (int o = 16; o; o >>= 1)
    #pragma unroll
    for (int r = 0; r < 4; r++) mx[r] = fmaxf(mx[r], __shfl_xor_sync(0xffffffffu, mx[r], o));

  for (int c = 0; c < nc; c++) {
    int j = c*32 + lane;
    float t[4];
    #pragma unroll
    for (int r = 0; r < 4; r++) t[r] = __expf(rows[r][j] - mx[r]);
    #pragma unroll
    for (int o = 16; o; o >>= 1)
      #pragma unroll
      for (int r = 0; r < 4; r++) t[r] += __shfl_xor_sync(0xffffffffu, t[r], o);
    if (lane == 0) {
      #pragma unroll
      for (int r = 0; r < 4; r++) csums[r*32 + c] = t[r];
    }
  }
  __syncwarp();

  float csv[4], incl[4], base[4], invz[4];
  #pragma unroll
  for (int r = 0; r < 4; r++) { csv[r] = (lane < nc) ? csums[r*32 + lane] : 0.f; incl[r] = csv[r]; }
  #pragma unroll
  for (int o = 1; o < 32; o <<= 1)
    #pragma unroll
    for (int r = 0; r < 4; r++) {
      float t = __shfl_up_sync(0xffffffffu, incl[r], o);
      if (lane >= o) incl[r] += t;
    }
  #pragma unroll
  for (int r = 0; r < 4; r++) {
    float z = __shfl_sync(0xffffffffu, incl[r], 31);
    base[r] = incl[r] - csv[r];
    invz[r] = __fdividef(1.f, z);
  }

  float m2[4] = {-INFINITY, -INFINITY, -INFINITY, -INFINITY};
  for (int c = 0; c < nc; c++) {
    int j = c*32 + lane;
    float sv[4], e[4];
    #pragma unroll
    for (int r = 0; r < 4; r++) { sv[r] = rows[r][j]; e[r] = __expf(sv[r] - mx[r]); }
    #pragma unroll
    for (int o = 1; o < 32; o <<= 1)
      #pragma unroll
      for (int r = 0; r < 4; r++) {
        float t = __shfl_up_sync(0xffffffffu, e[r], o);
        if (lane >= o) e[r] += t;
      }
    #pragma unroll
    for (int r = 0; r < 4; r++) {
      float cum = (__shfl_sync(0xffffffffu, base[r], c) + e[r]) * invz[r];
      float rem = 1.f - cum;
      float pos = fabsf((float)(gib + r - j));
      float dist = sqrtf(fmaxf(rem * pos, 0.f));
      float dec = fminf(fmaxf(__expf(dist * gmv), 1e-5f), 1e5f);
      float s2 = msk2<MODE>(gib + r, j) ? sv[r] * dec : NEGV;
      rows[r][j] = s2;
      m2[r] = fmaxf(m2[r], s2);
    }
  }
  #pragma unroll
  for (int o = 16; o; o >>= 1)
    #pragma unroll
    for (int r = 0; r < 4; r++) m2[r] = fmaxf(m2[r], __shfl_xor_sync(0xffffffffu, m2[r], o));

  float z2[4] = {0.f, 0.f, 0.f, 0.f};
  for (int c = 0; c < nc; c++) {
    int j = c*32 + lane;
    #pragma unroll
    for (int r = 0; r < 4; r++) {
      float e2 = __expf(rows[r][j] - m2[r]);
      rows[r][j] = e2; z2[r] += e2;
    }
  }
  #pragma unroll
  for (int o = 16; o; o >>= 1)
    #pragma unroll
    for (int r = 0; r < 4; r++) z2[r] += __shfl_xor_sync(0xffffffffu, z2[r], o);
  float scl[4];
  #pragma unroll
  for (int r = 0; r < 4; r++) {
    scl[r] = __fdividef(1.f, z2[r]);
    if (MAXOUT) scl[r] *= fminf(z2[r], 5.f);
    if (MODE == 1 && (gib + r) == 0) scl[r] = 0.f;   // fully-masked strict row -> 0
  }
  // pass 5 removed: masked entries are exactly 0 after pass 4 (exp underflow);
  // the 1/z2 (and maxout) scale is applied at the phase-3 output store.

  // ---- phase 3: out = (A_unnorm @ V) * scl ----
  float oa[4][2] = {};
  int d0 = 2*lane;
  for (int j0 = 0; j0 < jlim; j0 += 128) {
    __syncthreads();
    for (int idx = tid; idx < 128*16; idx += 256) {
      int rj = idx >> 4, dc = (idx & 15) << 2;
      *(float4*)&ks[rj*68 + dc] = *(const float4*)&vbase[(size_t)(j0 + rj)*DD + dc];
    }
    __syncthreads();
    int lim = jlim - j0; if (lim > 128) lim = 128;
    for (int jq = 0; jq < lim; jq += 4) {
      float4 af[4];
      #pragma unroll
      for (int r = 0; r < 4; r++)
        af[r] = *(const float4*)&srow[(wi*4 + r)*SS + j0 + jq];
      #pragma unroll
      for (int u = 0; u < 4; u++) {
        float2 vv = *(const float2*)&ks[(jq + u)*68 + d0];
        #pragma unroll
        for (int r = 0; r < 4; r++) {
          float a = (u == 0) ? af[r].x : (u == 1) ? af[r].y : (u == 2) ? af[r].z : af[r].w;
          oa[r][0] = fmaf(a, vv.x, oa[r][0]);
          oa[r][1] = fmaf(a, vv.y, oa[r][1]);
        }
      }
    }
  }
  #pragma unroll
  for (int r = 0; r < 4; r++) {
    float2 st; st.x = oa[r][0]*scl[r]; st.y = oa[r][1]*scl[r];
    *(float2*)&out[((size_t)b*SS + i0 + wi*4 + r)*DD + h*DKK + d0] = st;
  }
}

// ---------------------------------------------------------------------------
// Window attention (19 cols), one warp per (b,h,i)
// ---------------------------------------------------------------------------
__global__ __launch_bounds__(256) void win_kernel(
    const float* __restrict__ qw, const float* __restrict__ v,
    float* __restrict__ out, const float* __restrict__ gamma)
{
  int i = blockIdx.x;
  int b = blockIdx.y;
  int h = threadIdx.x >> 5;
  int lane = threadIdx.x & 31;
  const float* qbase = qw + (size_t)b*SS*DD + h*DKK;
  const float* vbase = v  + (size_t)b*SS*DD + h*DKK;
  float* obase = out + ((size_t)b*SS + i)*DD + h*DKK;
  int d0 = 2*lane;

  int wstart = i - 19; if (wstart < 0) wstart = 0;
  int n = i - wstart;
  if (n == 0) {
    float2 zz; zz.x = 0.f; zz.y = 0.f;
    *(float2*)(obase + d0) = zz;
    return;
  }
  bool act = lane < n;
  int j = wstart + lane;

  float s = NEGV;
  if (act) {
    const float4* q4 = (const float4*)(qbase + (size_t)i*DD);
    const float4* k4 = (const float4*)(qbase + (size_t)j*DD);
    float acc = 0.f;
    #pragma unroll
    for (int d4 = 0; d4 < 16; d4++) {
      float4 qa = q4[d4], kv = k4[d4];
      acc = fmaf(qa.x, kv.x, acc);
      acc = fmaf(qa.y, kv.y, acc);
      acc = fmaf(qa.z, kv.z, acc);
      acc = fmaf(qa.w, kv.w, acc);
    }
    s = acc * 0.125f;
  }
  float m = s;
  #pragma unroll
  for (int o = 16; o; o >>= 1) m = fmaxf(m, __shfl_xor_sync(0xffffffffu, m, o));
  float e = __expf(s - m);
  float incl = e;
  #pragma unroll
  for (int o = 1; o < 32; o <<= 1) {
    float t = __shfl_up_sync(0xffffffffu, incl, o);
    if (lane >= o) incl += t;
  }
  float z = __shfl_sync(0xffffffffu, incl, 31);
  float cum = incl * __fdividef(1.f, z);
  float rem = 1.f - cum;
  float pos = fabsf((float)(i - j));
  float dist = sqrtf(fmaxf(rem * pos, 0.f));
  float gmv = -fabsf(gamma[h]);
  float dec = fminf(fmaxf(__expf(dist * gmv), 1e-5f), 1e5f);
  float s2 = act ? s * dec : NEGV;
  float m2 = s2;
  #pragma unroll
  for (int o = 16; o; o >>= 1) m2 = fmaxf(m2, __shfl_xor_sync(0xffffffffu, m2, o));
  float e2 = __expf(s2 - m2);
  float z2 = e2;
  #pragma unroll
  for (int o = 16; o; o >>= 1) z2 += __shfl_xor_sync(0xffffffffu, z2, o);
  float a = act ? e2 * __fdividef(1.f, z2) : 0.f;

  float o0 = 0.f, o1 = 0.f;
  for (int jj = 0; jj < n; jj++) {
    float aj = __shfl_sync(0xffffffffu, a, jj);
    float2 vv = *(const float2*)(vbase + (size_t)(wstart + jj)*DD + d0);
    o0 = fmaf(aj, vv.x, o0);
    o1 = fmaf(aj, vv.y, o1);
  }
  float2 st; st.x = o0; st.y = o1;
  *(float2*)(obase + d0) = st;
}

// ---------------------------------------------------------------------------
// LayerNorm(x + y), z-batched over two independent problems (blockIdx.y)
// ---------------------------------------------------------------------------
__global__ __launch_bounds__(128) void ln_res_z_kernel(
    const float* __restrict__ x0, const float* __restrict__ y0,
    const float* __restrict__ lw0, const float* __restrict__ lb0,
    float* __restrict__ o0,
    const float* __restrict__ x1, const float* __restrict__ y1,
    const float* __restrict__ lw1, const float* __restrict__ lb1,
    float* __restrict__ o1)
{
  __shared__ float sb1[4], sb2[4];
  size_t row = blockIdx.x;
  const float* x; const float* y; const float* lw; const float* lb; float* out;
  if (blockIdx.y == 0) { x = x0; y = y0; lw = lw0; lb = lb0; out = o0; }
  else                 { x = x1; y = y1; lw = lw1; lb = lb1; out = o1; }
  const float* xr = x + row*DD;
  const float* yr = y + row*DD;
  int tid = threadIdx.x, lane = tid & 31, w = tid >> 5;
  float v[4]; float s = 0.f, q = 0.f;
  #pragma unroll
  for (int u = 0; u < 4; u++) {
    int c = tid + u*128;
    float t = xr[c] + yr[c];
    v[u] = t; s += t; q += t*t;
  }
  #pragma unroll
  for (int o = 16; o; o >>= 1) { s += __shfl_xor_sync(0xffffffffu, s, o); q += __shfl_xor_sync(0xffffffffu, q, o); }
  if (lane == 0) { sb1[w] = s; sb2[w] = q; }
  __syncthreads();
  s = sb1[0]+sb1[1]+sb1[2]+sb1[3];
  q = sb2[0]+sb2[1]+sb2[2]+sb2[3];
  float mu = s * (1.f/DD);
  float var = q * (1.f/DD) - mu*mu;
  float rs = rsqrtf(var + 1e-5f);
  #pragma unroll
  for (int u = 0; u < 4; u++) {
    int c = tid + u*128;
    out[row*DD + c] = (v[u]-mu)*rs*lw[c] + lb[c];
  }
}

// ---------------------------------------------------------------------------
// X[:, :512] = LN(hq+o), X[:, 512:] = LN(hq+o+ow)   (X has ld 1024)
// ---------------------------------------------------------------------------
__global__ __launch_bounds__(128) void fuse3_kernel(
    const float* __restrict__ hq, const float* __restrict__ o,
    const float* __restrict__ ow,
    const float* __restrict__ lw, const float* __restrict__ lb,
    float* __restrict__ X)
{
  __shared__ float sbuf[4][4];
  size_t row = blockIdx.x;
  int tid = threadIdx.x, lane = tid & 31, w = tid >> 5;
  const float* hr = hq + row*DD;
  const float* orr = o + row*DD;
  const float* owr = ow + row*DD;
  float v1[4], v2[4]; float st[4] = {0.f,0.f,0.f,0.f};
  #pragma unroll
  for (int u = 0; u < 4; u++) {
    int c = tid + u*128;
    float a  = hr[c] + orr[c];
    float b2 = a + owr[c];
    v1[u] = a; v2[u] = b2;
    st[0] += a;  st[1] += a*a;
    st[2] += b2; st[3] += b2*b2;
  }
  #pragma unroll
  for (int k = 0; k < 4; k++)
    #pragma unroll
    for (int o2 = 16; o2; o2 >>= 1) st[k] += __shfl_xor_sync(0xffffffffu, st[k], o2);
  if (lane == 0) { sbuf[0][w]=st[0]; sbuf[1][w]=st[1]; sbuf[2][w]=st[2]; sbuf[3][w]=st[3]; }
  __syncthreads();
  #pragma unroll
  for (int k = 0; k < 4; k++) st[k] = sbuf[k][0]+sbuf[k][1]+sbuf[k][2]+sbuf[k][3];
  float mu1 = st[0]*(1.f/DD), var1 = st[1]*(1.f/DD) - mu1*mu1;
  float mu2 = st[2]*(1.f/DD), var2 = st[3]*(1.f/DD) - mu2*mu2;
  float rs1 = rsqrtf(var1 + 1e-5f);
  float rs2 = rsqrtf(var2 + 1e-5f);
  #pragma unroll
  for (int u = 0; u < 4; u++) {
    int c = tid + u*128;
    X[row*1024 + c]       = (v1[u]-mu1)*rs1*lw[c] + lb[c];
    X[row*1024 + 512 + c] = (v2[u]-mu2)*rs2*lw[c] + lb[c];
  }
}

// ---------------------------------------------------------------------------
extern "C" void kernel_launch(void* const* d_in, const int* in_sizes, int n_in,
                              void* d_out, int out_size)
{
  const float* q_emb  = (const float*)d_in[0];
  const float* s_emb  = (const float*)d_in[1];
  const float* Wq     = (const float*)d_in[2];
  const float* bq     = (const float*)d_in[3];
  const float* Wqw    = (const float*)d_in[4];
  const float* bqw    = (const float*)d_in[5];
  const float* Wv     = (const float*)d_in[6];
  const float* bv     = (const float*)d_in[7];
  const float* Wo     = (const float*)d_in[8];
  const float* bo     = (const float*)d_in[9];
  const float* Wow    = (const float*)d_in[10];
  const float* bow    = (const float*)d_in[11];
  const float* gammas = (const float*)d_in[12];
  const float* ln_w   = (const float*)d_in[13];
  const float* ln_b   = (const float*)d_in[14];
  const float* Wc     = (const float*)d_in[15];
  const float* bc     = (const float*)d_in[16];
  float* outp = (float*)d_out;

  float* scratch = nullptr;
  cudaGetSymbolAddress((void**)&scratch, g_scratch);
  float* t0 = scratch;
  float* t1 = scratch + 1*(size_t)BSD;
  float* t2 = scratch + 2*(size_t)BSD;
  float* t3 = scratch + 3*(size_t)BSD;
  float* t4 = scratch + 4*(size_t)BSD;
  float* t5 = scratch + 5*(size_t)BSD;
  float* s6 = scratch + 6*(size_t)BSD;
  float* s7 = scratch + 7*(size_t)BSD;
  float* X  = t4;                        // [8192,1024] spans t4..t5 (used in tail)
  float* hqo = outp + (size_t)BSD;
  float* hso = outp + 2*(size_t)BSD;

  const int SMEM_ATTN = (32*SS + 32*68 + 128*68 + 8*128) * (int)sizeof(float); // 178688 B
  cudaFuncSetAttribute(attn2_kernel<0,0>, cudaFuncAttributeMaxDynamicSharedMemorySize, SMEM_ATTN);
  cudaFuncSetAttribute(attn2_kernel<1,1>, cudaFuncAttributeMaxDynamicSharedMemorySize, SMEM_ATTN);

  dim3 gdualz(8, 64, 2), gsingz(4, 64, 2);
  dim3 gseg3(12, 64);
  dim3 gsing(4, 64);
  dim3 gaz(SS/32, HH, 2*BB);
  dim3 ga1(SS/32, HH, BB);
  dim3 gw(SS, BB);
  dim3 glnz(BB*SS, 2);
  size_t DDl = (size_t)DD*DD;

  cudaStream_t s2str;
  cudaStreamCreateWithFlags(&s2str, cudaStreamNonBlocking);
  cudaEvent_t evA, evB;
  cudaEventCreateWithFlags(&evA, cudaEventDisableTiming);
  cudaEventCreateWithFlags(&evB, cudaEventDisableTiming);

  // ---- blocks 1+2 merged (independent streams via z-batching) ----
  gemm2z_kernel<<<gdualz, 256>>>(q_emb, s_emb,
                                 Wq, Wv, Wq + DDl, Wv + DDl,
                                 bq, bv, bq + DD, bv + DD,
                                 t0, t1, s6, s7, 512, 512);
  attn2_kernel<0,0><<<gaz, 256, SMEM_ATTN>>>(t0, t1, t2, s6, s7, t4, gammas);
  gemm2z_kernel<<<gsingz, 256>>>(t2, t4,
                                 Wo, Wo, Wo + DDl, Wo + DDl,
                                 bo, bo, bo + DD, bo + DD,
                                 t3, t3, t5, t5, 512, 512);
  ln_res_z_kernel<<<glnz, 128>>>(q_emb, t3, ln_w, ln_b, hqo,
                                 s_emb, t5, ln_w + DD, ln_b + DD, hso);

  // ---- block 3 ----
  gemm_seg3_kernel<<<gseg3, 256>>>(hqo, hso,
                                   Wq + 2*DDl, bq + 2*DD, t0,
                                   Wqw + 2*DDl, bqw + 2*DD, s6,
                                   Wv + 2*DDl, bv + 2*DD, t1);
  // fork: win (no smem) runs concurrently with the big attn launch
  cudaEventRecord(evA, 0);
  cudaStreamWaitEvent(s2str, evA, 0);
  win_kernel<<<gw, 256, 0, s2str>>>(s6, t1, t4, gammas + 2*HH);
  cudaEventRecord(evB, s2str);
  attn2_kernel<1,1><<<ga1, 256, SMEM_ATTN>>>(t0, t1, t2, t0, t1, t2, gammas + 2*HH);
  cudaStreamWaitEvent(0, evB, 0);   // join before o/ow GEMM (needs t4)
  gemm2z_kernel<<<gsingz, 256>>>(t2, t4,
                                 Wo + 2*DDl, Wo + 2*DDl, Wow, Wow,
                                 bo + 2*DD, bo + 2*DD, bow, bow,
                                 t3, t3, t0, t0, 512, 512);

  // ---- X = [LN(hq+o) | LN(hq+o+ow)] ; out = X @ Wc + bc ----
  fuse3_kernel<<<BB*SS, 128>>>(hqo, t3, t0, ln_w + 2*DD, ln_b + 2*DD, X);
  gemm2_kernel<<<gsing, 256>>>(X, 1024, Wc, Wc, bc, bc, outp, outp, 1024, 512);

  cudaEventDestroy(evA);
  cudaEventDestroy(evB);
  cudaStreamDestroy(s2str);
}